// round 8
// baseline (speedup 1.0000x reference)
#include <cuda_runtime.h>
#include <cstdint>
#include <cfloat>

// Problem constants (fixed by the dataset)
constexpr int Bv  = 16;      // batch
constexpr int Nv  = 16384;   // pixels
constexpr int Dv  = 64;      // embed dim
constexpr int Kv  = 64;      // templates
constexpr int D4v = Dv / 4;  // float4 chunks per vector (16)
constexpr int PPB = 2;       // pixels per block (warp-pair each -> all 4 SMSPs)
constexpr int KH  = 32;      // templates per staging half
constexpr float EPS = 1e-3f; // near-tie margin (>> fp32 dist error ~1e-5)

using ull = unsigned long long;

// XOR swizzle (conflict-free per 8-lane phase for all our access patterns)
__device__ __forceinline__ int tsw(int k, int d4) { return k * 16 + (d4 ^ (k & 7)); }
__device__ __forceinline__ int xsw(int b, int d4) { return b * 16 + (d4 ^ (b & 7)); }

__global__ __launch_bounds__(128, 6)
void osc_kernel(const float4* __restrict__ xg,     // frame_embeddings [B,N,D] f32
                const float4* __restrict__ tg,     // templates        [K,N,D] f32
                const int*    __restrict__ tcls,   // template_classes [K] int32
                float* __restrict__ out)
{
    __shared__ __align__(16) float4 ts[PPB][KH * 16];  // template half-tile (8KB/pixel)
    __shared__ __align__(16) float4 xs[PPB][Bv * 16];  // frame tiles (4KB/pixel)
    __shared__ float t2h[PPB][KH];                     // ||t_k||^2 for current half
    __shared__ float x2s[PPB][Bv];
    __shared__ float clsf[Kv];
    __shared__ float rv[PPB][Bv][17];                  // pitch 17: conflict-free scan
    __shared__ int   ri[PPB][Bv][17];
    __shared__ float bestvs[PPB][Bv];
    __shared__ int   bestks[PPB][Bv];
    __shared__ int   cnt[PPB][Bv];
    __shared__ ull   refined[PPB][Bv];

    const int tid = threadIdx.x;
    const int p   = tid >> 6;            // pixel slot 0/1 (warps 0,1 | 2,3)
    const int q   = tid & 63;            // thread id within pixel
    const int n   = blockIdx.x * PPB + p;

    // ---- stage frame tile (once) ----
#pragma unroll
    for (int i = 0; i < 4; ++i) {
        int idx = q + i * 64;            // 256 float4
        int b   = idx >> 4;
        int d4  = idx & 15;
        xs[p][xsw(b, d4)] = xg[((size_t)b * Nv + n) * D4v + d4];
    }
    if (tid < Kv) clsf[tid] = (float)tcls[tid];
    if (q < Bv) {
        cnt[p][q]     = 0;
        refined[p][q] = 0xFFFFFFFFFFFFFFFFULL;
    }
    __syncthreads();

    // ---- ||x_b||^2 (q<16) ----
    if (q < Bv) {
        float s0 = 0.f, s1 = 0.f, s2 = 0.f, s3 = 0.f;
#pragma unroll
        for (int d4 = 0; d4 < D4v; ++d4) {
            float4 v = xs[p][xsw(q, d4)];
            s0 = fmaf(v.x, v.x, s0); s1 = fmaf(v.y, v.y, s1);
            s2 = fmaf(v.z, v.z, s2); s3 = fmaf(v.w, v.w, s3);
        }
        x2s[p][q] = (s0 + s1) + (s2 + s3);
    }

    // thread tile coords: b in {c, c+4, c+8, c+12}; k local in {r, r+16}
    const int c = q & 3;
    const int r = q >> 2;

    float df[4][4];                      // distances [i][jj], k = 32*(jj>>1)+r+16*(jj&1)
    float bestv[4];                      // running min per b-index i
    int   bestk[4];
#pragma unroll
    for (int i = 0; i < 4; ++i) { bestv[i] = FLT_MAX; bestk[i] = Kv; }

    // ---- two k-halves: stage 32 rows, compute, convert to distances ----
#pragma unroll
    for (int h = 0; h < 2; ++h) {
        __syncthreads();                 // previous compute done before restage
        // stage template half (512 float4 per pixel, coalesced)
#pragma unroll
        for (int i = 0; i < 8; ++i) {
            int idx = q + i * 64;
            int kl  = idx >> 4;          // 0..31
            int d4  = idx & 15;
            ts[p][tsw(kl, d4)] = tg[((size_t)(h * KH + kl) * Nv + n) * D4v + d4];
        }
        __syncthreads();

        // ||t_k||^2 for this half (q<32: one row each)
        if (q < KH) {
            float s0 = 0.f, s1 = 0.f, s2 = 0.f, s3 = 0.f;
#pragma unroll
            for (int d4 = 0; d4 < D4v; ++d4) {
                float4 v = ts[p][tsw(q, d4)];
                s0 = fmaf(v.x, v.x, s0); s1 = fmaf(v.y, v.y, s1);
                s2 = fmaf(v.z, v.z, s2); s3 = fmaf(v.w, v.w, s3);
            }
            t2h[p][q] = (s0 + s1) + (s2 + s3);
        }
        __syncthreads();

        // 4b x 2k register tile for this half
        float acc[4][2];
#pragma unroll
        for (int i = 0; i < 4; ++i) { acc[i][0] = 0.f; acc[i][1] = 0.f; }

#pragma unroll 4
        for (int d4 = 0; d4 < D4v; ++d4) {
            float4 xv[4], tv[2];
#pragma unroll
            for (int i = 0; i < 4; ++i) xv[i] = xs[p][xsw(c + 4 * i, d4)];
            tv[0] = ts[p][tsw(r,      d4)];
            tv[1] = ts[p][tsw(r + 16, d4)];
#pragma unroll
            for (int i = 0; i < 4; ++i)
#pragma unroll
                for (int j = 0; j < 2; ++j) {
                    acc[i][j] = fmaf(xv[i].x, tv[j].x, acc[i][j]);
                    acc[i][j] = fmaf(xv[i].y, tv[j].y, acc[i][j]);
                    acc[i][j] = fmaf(xv[i].z, tv[j].z, acc[i][j]);
                    acc[i][j] = fmaf(xv[i].w, tv[j].w, acc[i][j]);
                }
        }

        // distances + running min (k ascending across halves => first-min kept)
#pragma unroll
        for (int i = 0; i < 4; ++i) {
            const float bx2 = x2s[p][c + 4 * i];
#pragma unroll
            for (int j = 0; j < 2; ++j) {
                const int kl = r + 16 * j;
                const float d = bx2 + t2h[p][kl] - 2.0f * acc[i][j];
                df[i][2 * h + j] = d;
                const int kg = h * KH + kl;
                if (d < bestv[i]) { bestv[i] = d; bestk[i] = kg; }
            }
        }
    }

    // ---- write per-thread partials; reduce across the 16 r's per b ----
#pragma unroll
    for (int i = 0; i < 4; ++i) {
        rv[p][c + 4 * i][r] = bestv[i];
        ri[p][c + 4 * i][r] = bestk[i];
    }
    __syncthreads();

    if (q < Bv) {
        float bv = rv[p][q][0];
        int   bk = ri[p][q][0];
#pragma unroll
        for (int t = 1; t < 16; ++t) {
            const float v = rv[p][q][t];
            const int   k = ri[p][q][t];
            if (v < bv || (v == bv && k < bk)) { bv = v; bk = k; }
        }
        bestvs[p][q] = bv;
        bestks[p][q] = bk;
    }
    __syncthreads();

    // ---- near-tie candidate count per b ----
#pragma unroll
    for (int i = 0; i < 4; ++i) {
        const int b = c + 4 * i;
        const float lim = bestvs[p][b] + EPS;
        int local = 0;
#pragma unroll
        for (int jj = 0; jj < 4; ++jj) local += (df[i][jj] <= lim) ? 1 : 0;
        if (local) atomicAdd(&cnt[p][b], local);
    }
    __syncthreads();

    // ---- Phase B (RARE): exact fp64 refinement, t re-read from GMEM ----
#pragma unroll
    for (int i = 0; i < 4; ++i) {
        const int b = c + 4 * i;
        if (cnt[p][b] < 2) continue;                  // uncontested: skip fp64
        const float lim = bestvs[p][b] + EPS;
#pragma unroll
        for (int jj = 0; jj < 4; ++jj) {
            if (df[i][jj] > lim) continue;
            const int k = (jj >> 1) * KH + r + 16 * (jj & 1);
            const float4* trow = &tg[((size_t)k * Nv + n) * D4v];
            double dd = 0.0;
            for (int d4 = 0; d4 < D4v; ++d4) {
                const float4 xv = xs[p][xsw(b, d4)];
                const float4 tv = __ldg(trow + d4);
                const double e0 = (double)xv.x - (double)tv.x;
                const double e1 = (double)xv.y - (double)tv.y;
                const double e2 = (double)xv.z - (double)tv.z;
                const double e3 = (double)xv.w - (double)tv.w;
                dd = fma(e0, e0, dd);
                dd = fma(e1, e1, dd);
                dd = fma(e2, e2, dd);
                dd = fma(e3, e3, dd);
            }
            const float dfx = (float)dd;              // exact -> fp32
            const ull key = ((ull)__float_as_uint(dfx) << 6) | (ull)k;
            atomicMin(&refined[p][b], key);
        }
    }
    __syncthreads();

    // ---- outputs ----
    if (q < Bv) {
        float bv;
        int   bk;
        if (cnt[p][q] >= 2) {
            const ull key = refined[p][q];
            bk = (int)(key & 63ULL);
            bv = __uint_as_float((unsigned int)(key >> 6));
        } else {
            bv = bestvs[p][q];
            bk = bestks[p][q];
        }
        const size_t BN = (size_t)Bv * Nv;
        const size_t o  = (size_t)q * Nv + n;
        out[o]           = (bv <= 0.5f) ? 1.0f : 0.0f;   // mask @ 0.5
        out[BN + o]      = (bv <= 1.0f) ? 1.0f : 0.0f;   // mask @ 1.0
        out[2 * BN + o]  = bv;                           // min_dists
        out[3 * BN + o]  = clsf[bk];                     // pred_classes
    }
}

extern "C" void kernel_launch(void* const* d_in, const int* in_sizes, int n_in,
                              void* d_out, int out_size)
{
    const float4* frame = (const float4*)d_in[0];   // [16,16384,64] f32
    const float4* tmpl  = (const float4*)d_in[1];   // [64,16384,64] f32
    const int*    tcls  = (const int*)d_in[2];      // [64] int32
    float*        out   = (float*)d_out;

    osc_kernel<<<Nv / PPB, 64 * PPB>>>(frame, tmpl, tcls, out);
}